// round 14
// baseline (speedup 1.0000x reference)
#include <cuda_runtime.h>
#include <cuda_fp16.h>
#include <math.h>

// ---------------------------------------------------------------------------
// FraudDetectionNet fused pipeline.
//
// qcontrib_p = t01^T C_p t23 with b_q=(1,cos p_q,sin p_q) (see prior rounds).
// C_p[s] = sum_m c_p[m] K[m][s];  K collapsed to 16 XOR/sign terms.
//
// Kernels:
//  1. kernelPre : build per-patch C (flat 84 = 81 + 3 zero-pad).
//  2. transK    : transpose images to patch-major fp16 pairs
//                 g_xt2[(2p+r)*NB + img] = (pix0, pix1) of patch row r,
//                 and compute per-image sum / sumsq -> g_S1/g_S2.
//  3. mainK     : 512 thr, 64 images/block (2/thread), grid 128 = 1 wave.
//                 C in smem (66KB); pixels via fully-coalesced LDG.32 of
//                 half2 (lane = image). No image staging, no phase barriers.
// ---------------------------------------------------------------------------

#define NPATCH   196
#define CPP      84          // 81 used + 3 zero-pad -> 21 float4 per patch
#define NB       8192        // max batch (layout stride)
#define NIMG     64
#define NTHREADS 512
#define NWARPS   16
#define SMEM_BYTES (NPATCH * CPP * 4)
#define TR_SMEM    (32 * 788 * 4)

__device__ float   g_C[NPATCH * CPP];
__device__ __half2 g_xt2[NPATCH * 2 * NB];   // 12.8MB, bss-zeroed
__device__ float   g_S1[NB], g_S2[NB];

// ---- fused precompute: K (collapsed form) + per-patch C -------------------
__global__ void kernelPre(const float* __restrict__ Ure,
                          const float* __restrict__ Uim,
                          const float* __restrict__ w_cls) {
    __shared__ float ur[256], ui[256];
    __shared__ float Ks[16 * 81];
    __shared__ float c[4][16];
    const int t = threadIdx.x;
    const int pbase = blockIdx.x * 4;

    ur[t] = Ure[t];
    ui[t] = Uim[t];
    if (t < 64) {
        int pp = t >> 4, m = t & 15;
        const float* wp = w_cls + 1 + 4 * (pbase + pp);
        float acc = 0.f;
#pragma unroll
        for (int w = 0; w < 4; ++w)
            acc = fmaf(1.f - 2.f * (float)((m >> (3 - w)) & 1), wp[w], acc);
        c[pp][m] = acc;
    }
    __syncthreads();

    for (int e = t; e < 16 * 81; e += 256) {
        int m = e / 81, s = e - m * 81;
        int s3 = s % 3, r = s / 3;
        int s2 = r % 3; r /= 3;
        int s1 = r % 3, s0 = r / 3;
        int mask = ((int)(s0 == 2) << 3) | ((int)(s1 == 2) << 2)
                 | ((int)(s2 == 2) << 1) | (int)(s3 == 2);
        int neg  = ((int)(s0 == 1) << 3) | ((int)(s1 == 1) << 2)
                 | ((int)(s2 == 1) << 1) | (int)(s3 == 1);
        const float* urm = ur + m * 16;
        const float* uim = ui + m * 16;
        float acc = 0.f;
#pragma unroll
        for (int n = 0; n < 16; ++n) {
            float v = urm[n] * urm[n ^ mask] + uim[n] * uim[n ^ mask];
            acc += (__popc(n & neg) & 1) ? -v : v;
        }
        Ks[e] = acc * 0.0625f;
    }
    __syncthreads();

    for (int e = t; e < 4 * CPP; e += 256) {
        int pp = e / CPP, k = e - pp * CPP;
        float v = 0.f;
        if (k < 81) {
#pragma unroll
            for (int m = 0; m < 16; ++m) v = fmaf(c[pp][m], Ks[m * 81 + k], v);
        }
        g_C[(pbase + pp) * CPP + k] = v;
    }
}

// ---- transpose to patch-major fp16 + per-image stats ----------------------
// grid = (B+31)/32 blocks of 256 threads; 32 images per block.
__global__ void __launch_bounds__(256, 2)
transK(const float* __restrict__ x, int B) {
    extern __shared__ float xs[];        // 32 * 788 floats
    const int tid  = threadIdx.x;
    const int w    = tid >> 5;
    const int lane = tid & 31;
    const int img0 = blockIdx.x * 32;

    // stage 4 images per warp (coalesced float4) + stats
    float ls1[4] = {0.f, 0.f, 0.f, 0.f};
    float ls2[4] = {0.f, 0.f, 0.f, 0.f};
#pragma unroll
    for (int j = 0; j < 4; ++j) {
        int img = w + 8 * j;
        if (img0 + img < B) {
            const float4* src = (const float4*)(x + (size_t)(img0 + img) * 784);
            float* dst = xs + img * 788;
            for (int k = lane; k < 196; k += 32) {
                float4 v = src[k];
                dst[4 * k + 0] = v.x; dst[4 * k + 1] = v.y;
                dst[4 * k + 2] = v.z; dst[4 * k + 3] = v.w;
                ls1[j] += (v.x + v.y) + (v.z + v.w);
                ls2[j] = fmaf(v.x, v.x, fmaf(v.y, v.y,
                         fmaf(v.z, v.z, fmaf(v.w, v.w, ls2[j]))));
            }
        }
    }
#pragma unroll
    for (int j = 0; j < 4; ++j) {
        float a = ls1[j], b = ls2[j];
#pragma unroll
        for (int o = 16; o > 0; o >>= 1) {
            a += __shfl_down_sync(0xffffffffu, a, o);
            b += __shfl_down_sync(0xffffffffu, b, o);
        }
        int img = img0 + w + 8 * j;
        if (lane == 0 && img < B) { g_S1[img] = a; g_S2[img] = b; }
    }
    __syncthreads();

    // write out: thread (i = tid&31 image, pp = tid>>5 patch lane)
    const int i  = tid & 31;
    const int pp = tid >> 5;
    if (img0 + i < B) {
        const float* xi = xs + i * 788;
        for (int p = pp; p < NPATCH; p += 8) {
            int pr = p / 14, pc = p - pr * 14;
            int off = pr * 56 + pc * 2;
            float2 tp = *(const float2*)(xi + off);
            float2 bt = *(const float2*)(xi + off + 28);
            g_xt2[(size_t)(2 * p + 0) * NB + img0 + i] = __floats2half2_rn(tp.x, tp.y);
            g_xt2[(size_t)(2 * p + 1) * NB + img0 + i] = __floats2half2_rn(bt.x, bt.y);
        }
    }
}

// ---- main fused kernel: 64 images/block, 2/thread, coalesced gt loads -----
__global__ void __launch_bounds__(NTHREADS, 1)
mainK(const float* __restrict__ w_in,   const float* __restrict__ b_in,
      const float* __restrict__ scale_in, const float* __restrict__ shift_in,
      const float* __restrict__ Wc,     const float* __restrict__ bc,
      const float* __restrict__ scalec, const float* __restrict__ shiftc,
      const float* __restrict__ w_out,  const float* __restrict__ b_out,
      const float* __restrict__ w_cls,  const float* __restrict__ b_cls,
      float* __restrict__ out, int B, int L)
{
    extern __shared__ float Cs[];        // NPATCH*CPP floats
    __shared__ float rq[NWARPS][NIMG];

    const int tid  = threadIdx.x;
    const int w    = tid >> 5;
    const int lane = tid & 31;
    const int img_base = blockIdx.x * NIMG;
    int nimg = B - img_base;
    if (nimg > NIMG) nimg = NIMG;

    // stage C
    {
        const float4* gc4 = (const float4*)g_C;
        float4* cs4 = (float4*)Cs;
        for (int i = tid; i < NPATCH * CPP / 4; i += NTHREADS) cs4[i] = gc4[i];
    }
    __syncthreads();

    const bool hasA = lane < nimg;
    const bool hasB = (lane + 32) < nimg;
    const int iA = img_base + lane;              // reads clamped by array size
    const int iB = img_base + lane + 32 < NB ? img_base + lane + 32 : 0;

    float qA = 0.f, qB = 0.f;
    {
        const int ps = (w * NPATCH) / NWARPS;
        const int pe = ((w + 1) * NPATCH) / NWARPS;
        const __half2* gp = g_xt2 + (size_t)(2 * ps) * NB;

        // prefetch first patch
        __half2 htA = gp[iA],      hbA = gp[NB + iA];
        __half2 htB = gp[iB],      hbB = gp[NB + iB];
        gp += 2 * NB;

        for (int p = ps; p < pe; ++p) {
            float2 cA0 = __half22float2(htA), cA1 = __half22float2(hbA);
            float2 cB0 = __half22float2(htB), cB1 = __half22float2(hbB);
            if (p + 1 < pe) {
                htA = gp[iA]; hbA = gp[NB + iA];
                htB = gp[iB]; hbB = gp[NB + iB];
                gp += 2 * NB;
            }

            float ta[9], tb[9];
            float a0c, a0s, a1c, a1s, a2c, a2s, a3c, a3s;
            __sincosf(cA0.x, &a0s, &a0c);
            __sincosf(cA0.y, &a1s, &a1c);
            __sincosf(cA1.x, &a2s, &a2c);
            __sincosf(cA1.y, &a3s, &a3c);
            ta[0] = 1.f;
            ta[1] = a3c;        ta[2] = a3s;
            ta[3] = a2c;        ta[4] = a2c * a3c;
            ta[5] = a2c * a3s;  ta[6] = a2s;
            ta[7] = a2s * a3c;  ta[8] = a2s * a3s;

            float b0c, b0s, b1c, b1s, b2c, b2s, b3c, b3s;
            __sincosf(cB0.x, &b0s, &b0c);
            __sincosf(cB0.y, &b1s, &b1c);
            __sincosf(cB1.x, &b2s, &b2c);
            __sincosf(cB1.y, &b3s, &b3c);
            tb[0] = 1.f;
            tb[1] = b3c;        tb[2] = b3s;
            tb[3] = b2c;        tb[4] = b2c * b3c;
            tb[5] = b2c * b3s;  tb[6] = b2s;
            tb[7] = b2s * b3c;  tb[8] = b2s * b3s;

            const float4* Cp4 = (const float4*)(Cs + p * CPP);
            float dA[9], dB[9];
#pragma unroll
            for (int q = 0; q < 21; ++q) {
                float4 f = Cp4[q];
#pragma unroll
                for (int u = 0; u < 4; ++u) {
                    int k = 4 * q + u;
                    if (k >= 81) break;
                    float v = (u == 0) ? f.x : (u == 1) ? f.y : (u == 2) ? f.z : f.w;
                    int i = k / 9, j = k - 9 * i;
                    if (j == 0) { dA[i] = v;            dB[i] = v; }
                    else        { dA[i] = fmaf(v, ta[j], dA[i]);
                                  dB[i] = fmaf(v, tb[j], dB[i]); }
                }
            }
            float eA0 = fmaf(dA[2], a1s, fmaf(dA[1], a1c, dA[0]));
            float eA1 = fmaf(dA[5], a1s, fmaf(dA[4], a1c, dA[3]));
            float eA2 = fmaf(dA[8], a1s, fmaf(dA[7], a1c, dA[6]));
            qA = fmaf(eA2, a0s, fmaf(eA1, a0c, eA0 + qA));
            float eB0 = fmaf(dB[2], b1s, fmaf(dB[1], b1c, dB[0]));
            float eB1 = fmaf(dB[5], b1s, fmaf(dB[4], b1c, dB[3]));
            float eB2 = fmaf(dB[8], b1s, fmaf(dB[7], b1c, dB[6]));
            qB = fmaf(eB2, b0s, fmaf(eB1, b0c, eB0 + qB));
        }
    }

    rq[w][lane]      = hasA ? qA : 0.f;
    rq[w][lane + 32] = hasB ? qB : 0.f;
    __syncthreads();

    if (tid < NIMG && tid < nimg) {
        float Q = 0.f;
#pragma unroll
        for (int k = 0; k < NWARPS; ++k) Q += rq[k][tid];
        float S1 = g_S1[img_base + tid], S2 = g_S2[img_base + tid];
        float mean = S1 * (1.f / 784.f);
        float var  = (S2 - S1 * S1 * (1.f / 784.f)) * (1.f / 783.f);
        float stdv = sqrtf(fmaxf(var, 0.f));
        float h0 = tanhf(fmaf(mean, w_in[0], fmaf(stdv, w_in[1], b_in[0]))) * scale_in[0] + shift_in[0];
        float h1 = tanhf(fmaf(mean, w_in[2], fmaf(stdv, w_in[3], b_in[1]))) * scale_in[1] + shift_in[1];
        for (int i = 0; i < L; ++i) {
            float n0 = tanhf(fmaf(h0, Wc[i*4+0], fmaf(h1, Wc[i*4+1], bc[i*2+0]))) * scalec[i*2+0] + shiftc[i*2+0];
            float n1 = tanhf(fmaf(h0, Wc[i*4+2], fmaf(h1, Wc[i*4+3], bc[i*2+1]))) * scalec[i*2+1] + shiftc[i*2+1];
            h0 = n0; h1 = n1;
        }
        float cls   = fmaf(h0, w_out[0], fmaf(h1, w_out[1], b_out[0]));
        float logit = fmaf(cls, w_cls[0], Q + b_cls[0]);
        out[img_base + tid] = 1.f / (1.f + expf(-logit));
    }
}

extern "C" void kernel_launch(void* const* d_in, const int* in_sizes, int n_in,
                              void* d_out, int out_size) {
    const float* x        = (const float*)d_in[0];
    const float* w_in     = (const float*)d_in[1];
    const float* b_in     = (const float*)d_in[2];
    const float* scale_in = (const float*)d_in[3];
    const float* shift_in = (const float*)d_in[4];
    const float* Wc       = (const float*)d_in[5];
    const float* bc       = (const float*)d_in[6];
    const float* scalec   = (const float*)d_in[7];
    const float* shiftc   = (const float*)d_in[8];
    const float* w_out    = (const float*)d_in[9];
    const float* b_out    = (const float*)d_in[10];
    const float* U_re     = (const float*)d_in[11];
    const float* U_im     = (const float*)d_in[12];
    const float* w_cls    = (const float*)d_in[13];
    const float* b_cls    = (const float*)d_in[14];
    float* out = (float*)d_out;

    int B = in_sizes[0] / 784;
    int L = in_sizes[5] / 4;

    cudaFuncSetAttribute(mainK,  cudaFuncAttributeMaxDynamicSharedMemorySize, SMEM_BYTES);
    cudaFuncSetAttribute(transK, cudaFuncAttributeMaxDynamicSharedMemorySize, TR_SMEM);

    kernelPre<<<NPATCH / 4, 256>>>(U_re, U_im, w_cls);
    transK<<<(B + 31) / 32, 256, TR_SMEM>>>(x, B);
    mainK<<<(B + NIMG - 1) / NIMG, NTHREADS, SMEM_BYTES>>>(
        w_in, b_in, scale_in, shift_in, Wc, bc, scalec, shiftc,
        w_out, b_out, w_cls, b_cls, out, B, L);
}